// round 12
// baseline (speedup 1.0000x reference)
#include <cuda_runtime.h>
#include <cstdint>

static constexpr int D      = 128;
static constexpr int K      = 8;
static constexpr int WARPS  = 8;      // per block (256 threads)
static constexpr int ITERS  = 9;      // iterations per warp (18 pairs) -> single wave
static constexpr int PPI    = 2;      // pairs per iteration
static constexpr int STAGE_FLOATS = PPI * 2 * D;      // 512 floats = 2048 B
static constexpr int STAGE_BYTES  = STAGE_FLOATS * 4; // 2048
static constexpr int ROW_BYTES    = D * 4;            // 512

__global__ void spl_zero_kernel(float* out) { *out = 0.0f; }

__device__ __forceinline__ void cpa16(uint32_t dst, const float* src) {
    asm volatile("cp.async.cg.shared.global [%0], [%1], 16;\n" :: "r"(dst), "l"(src));
}
__device__ __forceinline__ void cpa_commit() {
    asm volatile("cp.async.commit_group;\n" ::: "memory");
}
__device__ __forceinline__ void cpa_wait1() {
    asm volatile("cp.async.wait_group 1;\n" ::: "memory");
}

__global__ __launch_bounds__(256, 5) void spl_loss_kernel(
    const float* __restrict__ emb,
    const int*   __restrict__ pair_ids,
    const int*   __restrict__ dims,
    float*       __restrict__ out,
    int n_pairs, float inv_p)
{
    const unsigned FULL = 0xFFFFFFFFu;
    const int lane = threadIdx.x & 31;
    const int wid  = threadIdx.x >> 5;

    __shared__ float rows[WARPS][2 * STAGE_FLOATS];   // 8 x 4KB = 32KB (double buffer)
    __shared__ float warp_sums[WARPS];

    const int  warp_global = blockIdx.x * WARPS + wid;
    const int  base        = warp_global * (PPI * ITERS);   // first pair (even)
    const int  wg9         = warp_global * ITERS;           // int4 index base
    float*     mybuf       = rows[wid];
    uint32_t   sb = (uint32_t)__cvta_generic_to_shared(mybuf) + lane * 16;

    const int  id4_max = (n_pairs >> 1) - 1;
    const long dim_max = (long)n_pairs * K - 1;

    float c = 0.0f;
    if (base < n_pairs) {
        auto load_ids = [&](int i) -> int4 {
            int idx = wg9 + i;
            if (idx > id4_max) idx = id4_max;
            return __ldg((const int4*)pair_ids + idx);
        };
        auto load_dim = [&](int i) -> int {
            long idx = (long)(base + PPI * i) * K + lane;   // lanes 0..15 used
            if (idx > dim_max) idx = dim_max;
            return __ldg(dims + idx);
        };
        auto valid = [&](int i, int sub) { return base + PPI * i + sub < n_pairs; };
        auto issue_stage = [&](int s, int4 pr, bool v0, bool v1) {
            uint32_t dst = sb + (uint32_t)s * STAGE_BYTES;
            if (v0) {
                cpa16(dst,                 emb + (size_t)pr.x * D + lane * 4);
                cpa16(dst + ROW_BYTES,     emb + (size_t)pr.y * D + lane * 4);
            }
            if (v1) {
                cpa16(dst + 2 * ROW_BYTES, emb + (size_t)pr.z * D + lane * 4);
                cpa16(dst + 3 * ROW_BYTES, emb + (size_t)pr.w * D + lane * 4);
            }
        };

        // ---- prologue (identical scheme to the proven R7 pipeline) ----
        int4 id_q[2];
        int  dim_q[4];
        id_q[0]  = load_ids(0);
        dim_q[0] = load_dim(0);
        issue_stage(0, id_q[0], valid(0, 0), valid(0, 1));
        cpa_commit();
        id_q[1]  = load_ids(1);
        dim_q[1] = load_dim(1);

        #pragma unroll
        for (int i = 0; i < ITERS; i++) {
            // 1) issue prefetch for iter i+1 (slot held stage i-1: reads done)
            if (i + 1 < ITERS)
                issue_stage((i + 1) & 1, id_q[(i + 1) & 1], valid(i + 1, 0), valid(i + 1, 1));
            cpa_commit();   // uniform group accounting

            // 2) start index loads for iter i+2
            if (i + 2 < ITERS) {
                id_q[i & 1]        = load_ids(i + 2);
                dim_q[(i + 2) & 3] = load_dim(i + 2);
            }

            // 3) wait for stage i, make cp.async writes cross-lane visible
            cpa_wait1();
            __syncwarp();

            const float* buf = mybuf + (i & 1) * STAGE_FLOATS;
            const bool v0 = valid(i, 0);
            const bool v1 = valid(i, 1);

            // polarity gathers from smem rows; lanes 0-7 pair0, 8-15 pair1
            const int  mydim = dim_q[i & 3];
            const bool pol   = (lane < 8) ? v0 : (lane < 16 && v1);
            float g1 = 0.0f, g2 = 0.0f;
            if (pol) {
                int rs = (lane >> 3) * 256;
                g1 = buf[rs + mydim];
                g2 = buf[rs + 128 + mydim];
            }

            // duplicate-dim detection: one MATCH + one ballot (exact dedup)
            int key = pol ? (mydim + ((lane & 8) << 5)) : (0x8000 + lane);
            unsigned mm = __match_any_sync(FULL, key);
            bool leader = ((mm & ((1u << lane) - 1u)) == 0u);
            unsigned lb = __ballot_sync(FULL, leader && pol);
            int d0 = __popc(lb & 0x00FFu);
            int d1 = __popc(lb & 0xFF00u);
            float invk0 = v0 ? __fdividef(0.5f, (float)(D - d0)) : 0.0f;
            float invk1 = v1 ? __fdividef(0.5f, (float)(D - d1)) : 0.0f;

            // full-row diff^2 totals (guarded smem reads; invalid pairs skipped)
            float t0 = 0.0f, t1 = 0.0f;
            if (v0) {
                float4 A = ((const float4*)buf)[lane];
                float4 B = ((const float4*)(buf + 128))[lane];
                float dx = A.x - B.x, dy = A.y - B.y, dz = A.z - B.z, dw = A.w - B.w;
                t0 = fmaf(dx, dx, fmaf(dy, dy, fmaf(dz, dz, dw * dw)));
            }
            if (v1) {
                float4 A = ((const float4*)(buf + 256))[lane];
                float4 B = ((const float4*)(buf + 384))[lane];
                float dx = A.x - B.x, dy = A.y - B.y, dz = A.z - B.z, dw = A.w - B.w;
                t1 = fmaf(dx, dx, fmaf(dy, dy, fmaf(dz, dz, dw * dw)));
            }
            c = fmaf(t0, invk0, fmaf(t1, invk1, c));

            if (pol) {
                // polarity (duplicates counted; sign_prod==0 iff either value is +-0)
                float sm  = fabsf(g1) + fabsf(g2);
                bool zero = (g1 == 0.0f) || (g2 == 0.0f);
                bool opp  = ((__float_as_int(g1) ^ __float_as_int(g2)) < 0);
                c += zero ? 0.1f : (opp ? -0.5f * sm : sm);
                if (leader) {   // subtract selected-dim diff^2 (distinct dims only)
                    float dd = g1 - g2;
                    c = fmaf(-dd * dd, (lane & 8) ? invk1 : invk0, c);
                }
            }
            __syncwarp();       // stage-reuse safety before next overwrite
        }
    }

    // ---- warp butterfly + block reduce + one atomic per block ----
    #pragma unroll
    for (int off = 16; off > 0; off >>= 1)
        c += __shfl_xor_sync(FULL, c, off);
    if (lane == 0) warp_sums[wid] = c;
    __syncthreads();
    if (threadIdx.x == 0) {
        float s = 0.0f;
        #pragma unroll
        for (int v = 0; v < WARPS; v++) s += warp_sums[v];
        atomicAdd(out, s * inv_p);
    }
}

extern "C" void kernel_launch(void* const* d_in, const int* in_sizes, int n_in,
                              void* d_out, int out_size)
{
    const float* emb      = (const float*)d_in[0];  // (VOCAB, 128) f32
    const int*   pair_ids = (const int*)  d_in[1];  // (P, 2) i32
    const int*   dims     = (const int*)  d_in[2];  // (P, 8) i32
    float*       out      = (float*)d_out;          // scalar f32

    int n_pairs = in_sizes[1] / 2;
    spl_zero_kernel<<<1, 1>>>(out);

    // 18 pairs/warp -> 695 blocks for P=100000: fits one residency wave
    // (5 blocks/SM x 148 SMs = 740), eliminating the straggler wave.
    int pairs_per_warp = PPI * ITERS;                        // 18
    int warps_needed   = (n_pairs + pairs_per_warp - 1) / pairs_per_warp;
    int blocks         = (warps_needed + WARPS - 1) / WARPS;
    spl_loss_kernel<<<blocks, 256>>>(emb, pair_ids, dims, out,
                                     n_pairs, 1.0f / (float)n_pairs);
}

// round 14
// speedup vs baseline: 1.3658x; 1.3658x over previous
#include <cuda_runtime.h>
#include <cstdint>

static constexpr int D      = 128;
static constexpr int K      = 8;
static constexpr int WARPS  = 8;      // per block (256 threads)
static constexpr int ITERS  = 9;      // 18 pairs/warp -> 695 blocks (single wave @6/SM)
static constexpr int PPI    = 2;      // pairs per iteration
static constexpr int STAGE_FLOATS = PPI * 2 * D;      // 512 floats = 2048 B
static constexpr int STAGE_BYTES  = STAGE_FLOATS * 4; // 2048
static constexpr int ROW_BYTES    = D * 4;            // 512

__global__ void spl_zero_kernel(float* out) { *out = 0.0f; }

__device__ __forceinline__ void cpa16(uint32_t dst, const float* src) {
    asm volatile("cp.async.cg.shared.global [%0], [%1], 16;\n" :: "r"(dst), "l"(src));
}
__device__ __forceinline__ void cpa_commit() {
    asm volatile("cp.async.commit_group;\n" ::: "memory");
}
__device__ __forceinline__ void cpa_wait1() {
    asm volatile("cp.async.wait_group 1;\n" ::: "memory");
}

// Per-warp pipelined work. TAIL=false: all 18 pairs valid, no guards/clamps.
template<bool TAIL>
__device__ __forceinline__ float warp_work(
    const float* __restrict__ emb,
    const int*   __restrict__ pair_ids,
    const int*   __restrict__ dims,
    float* mybuf, unsigned* mymarks,
    int warp_global, int lane, int n_pairs)
{
    const unsigned FULL = 0xFFFFFFFFu;
    const int  base    = warp_global * (PPI * ITERS);
    const int  wgI     = warp_global * ITERS;
    uint32_t   sb      = (uint32_t)__cvta_generic_to_shared(mybuf) + lane * 16;
    const int  id4_max = (n_pairs >> 1) - 1;
    const long dim_max = (long)n_pairs * K - 1;

    auto load_ids = [&](int i) -> int4 {
        int idx = wgI + i;
        if (TAIL && idx > id4_max) idx = id4_max;
        return __ldg((const int4*)pair_ids + idx);
    };
    auto load_dim = [&](int i) -> int {
        long idx = (long)(base + PPI * i) * K + lane;   // lanes 0..15 used
        if (TAIL && idx > dim_max) idx = dim_max;
        return __ldg(dims + idx);
    };
    auto valid = [&](int i, int sub) {
        return TAIL ? (base + PPI * i + sub < n_pairs) : true;
    };
    auto issue_stage = [&](int s, int4 pr, bool v0, bool v1) {
        uint32_t dst = sb + (uint32_t)s * STAGE_BYTES;
        if (v0) {
            cpa16(dst,                 emb + (size_t)pr.x * D + lane * 4);
            cpa16(dst + ROW_BYTES,     emb + (size_t)pr.y * D + lane * 4);
        }
        if (v1) {
            cpa16(dst + 2 * ROW_BYTES, emb + (size_t)pr.z * D + lane * 4);
            cpa16(dst + 3 * ROW_BYTES, emb + (size_t)pr.w * D + lane * 4);
        }
    };

    // ---- prologue ----
    int4 id_q[2];
    int  dim_q[4];
    id_q[0]  = load_ids(0);
    dim_q[0] = load_dim(0);
    issue_stage(0, id_q[0], valid(0, 0), valid(0, 1));
    cpa_commit();
    id_q[1]  = load_ids(1);
    dim_q[1] = load_dim(1);

    float c = 0.0f;
    #pragma unroll
    for (int i = 0; i < ITERS; i++) {
        // 1) issue prefetch for iter i+1 (slot last read in iter i-1, fenced below)
        if (i + 1 < ITERS)
            issue_stage((i + 1) & 1, id_q[(i + 1) & 1], valid(i + 1, 0), valid(i + 1, 1));
        cpa_commit();   // uniform group accounting

        // 2) start index loads for iter i+2
        if (i + 2 < ITERS) {
            id_q[i & 1]        = load_ids(i + 2);
            dim_q[(i + 2) & 3] = load_dim(i + 2);
        }

        // 3) wait for stage i, make cp.async writes cross-lane visible
        cpa_wait1();
        __syncwarp();

        const float* buf = mybuf + (i & 1) * STAGE_FLOATS;
        const bool v0 = valid(i, 0);
        const bool v1 = valid(i, 1);

        // marks: byte-flags for this iteration's selected dims (both pairs)
        mymarks[lane]      = 0u;
        mymarks[lane + 32] = 0u;
        __syncwarp();
        const int  mydim = dim_q[i & 3];
        const bool pol   = (lane < 8) ? v0 : (lane < 16 && v1);
        float g1 = 0.0f, g2 = 0.0f;
        if (pol) {
            int rs = (lane >> 3) * 256;
            ((unsigned char*)mymarks)[((lane >> 3) << 7) + mydim] = 1;
            g1 = buf[rs + mydim];
            g2 = buf[rs + 128 + mydim];
        }
        __syncwarp();
        unsigned w0 = mymarks[lane];
        unsigned w1 = mymarks[lane + 32];

        // polarity (duplicates counted; sign_prod==0 iff either value is +-0)
        if (pol) {
            float sm  = fabsf(g1) + fabsf(g2);
            bool zero = (g1 == 0.0f) || (g2 == 0.0f);
            bool opp  = ((__float_as_int(g1) ^ __float_as_int(g2)) < 0);
            c += zero ? 0.1f : (opp ? -0.5f * sm : sm);
        }

        // distinct-dim counts (warp-collective)
        unsigned d0 = __reduce_add_sync(FULL, (w0 * 0x01010101u) >> 24);
        unsigned d1 = __reduce_add_sync(FULL, (w1 * 0x01010101u) >> 24);

        if (v0) {
            float4 A = ((const float4*)buf)[lane];
            float4 B = ((const float4*)(buf + 128))[lane];
            float dx = A.x - B.x, dy = A.y - B.y, dz = A.z - B.z, dw = A.w - B.w;
            float kept = 0.0f;
            if (!(w0 & 0x000000FFu)) kept = fmaf(dx, dx, kept);
            if (!(w0 & 0x0000FF00u)) kept = fmaf(dy, dy, kept);
            if (!(w0 & 0x00FF0000u)) kept = fmaf(dz, dz, kept);
            if (!(w0 & 0xFF000000u)) kept = fmaf(dw, dw, kept);
            c = fmaf(kept, __fdividef(0.5f, (float)(D - (int)d0)), c);
        }
        if (v1) {
            float4 A = ((const float4*)(buf + 256))[lane];
            float4 B = ((const float4*)(buf + 384))[lane];
            float dx = A.x - B.x, dy = A.y - B.y, dz = A.z - B.z, dw = A.w - B.w;
            float kept = 0.0f;
            if (!(w1 & 0x000000FFu)) kept = fmaf(dx, dx, kept);
            if (!(w1 & 0x0000FF00u)) kept = fmaf(dy, dy, kept);
            if (!(w1 & 0x00FF0000u)) kept = fmaf(dz, dz, kept);
            if (!(w1 & 0xFF000000u)) kept = fmaf(dw, dw, kept);
            c = fmaf(kept, __fdividef(0.5f, (float)(D - (int)d1)), c);
        }
        __syncwarp();   // stage-reuse safety before next overwrite
    }
    return c;
}

__global__ __launch_bounds__(256, 6) void spl_loss_kernel(
    const float* __restrict__ emb,
    const int*   __restrict__ pair_ids,
    const int*   __restrict__ dims,
    float*       __restrict__ out,
    int n_pairs, float inv_p)
{
    const unsigned FULL = 0xFFFFFFFFu;
    const int lane = threadIdx.x & 31;
    const int wid  = threadIdx.x >> 5;

    __shared__ float    rows[WARPS][2 * STAGE_FLOATS];   // 32 KB double buffer
    __shared__ unsigned marks[WARPS][64];                // 2 KB
    __shared__ float    warp_sums[WARPS];

    const int warp_global = blockIdx.x * WARPS + wid;
    const int base        = warp_global * (PPI * ITERS);

    float c = 0.0f;
    if (base + PPI * ITERS <= n_pairs) {
        c = warp_work<false>(emb, pair_ids, dims, rows[wid], marks[wid],
                             warp_global, lane, n_pairs);
    } else if (base < n_pairs) {
        c = warp_work<true>(emb, pair_ids, dims, rows[wid], marks[wid],
                            warp_global, lane, n_pairs);
    }

    // ---- warp butterfly + block reduce + one atomic per block ----
    #pragma unroll
    for (int off = 16; off > 0; off >>= 1)
        c += __shfl_xor_sync(FULL, c, off);
    if (lane == 0) warp_sums[wid] = c;
    __syncthreads();
    if (threadIdx.x == 0) {
        float s = 0.0f;
        #pragma unroll
        for (int v = 0; v < WARPS; v++) s += warp_sums[v];
        atomicAdd(out, s * inv_p);
    }
}

extern "C" void kernel_launch(void* const* d_in, const int* in_sizes, int n_in,
                              void* d_out, int out_size)
{
    const float* emb      = (const float*)d_in[0];  // (VOCAB, 128) f32
    const int*   pair_ids = (const int*)  d_in[1];  // (P, 2) i32
    const int*   dims     = (const int*)  d_in[2];  // (P, 8) i32
    float*       out      = (float*)d_out;          // scalar f32

    int n_pairs = in_sizes[1] / 2;
    spl_zero_kernel<<<1, 1>>>(out);

    // 18 pairs/warp -> 695 blocks (P=100000); 6 blocks/SM x 148 SMs = 888
    // resident -> single wave, no straggler tail.
    int pairs_per_warp = PPI * ITERS;                        // 18
    int warps_needed   = (n_pairs + pairs_per_warp - 1) / pairs_per_warp;
    int blocks         = (warps_needed + WARPS - 1) / WARPS;
    spl_loss_kernel<<<blocks, 256>>>(emb, pair_ids, dims, out,
                                     n_pairs, 1.0f / (float)n_pairs);
}